// round 9
// baseline (speedup 1.0000x reference)
#include <cuda_runtime.h>
#include <cuda_fp16.h>
#include <cstdint>

// ============================================================================
// Binarized-weight 3x3 conv, stride 1, pad 1, via implicit GEMM on HMMA
// (mma.sync m16n8k16 fp16 -> fp32 accum; arch-neutral PTX at compute_103).
// x: (32,128,64,64) f32 NCHW ; w: (256,128,3,3) f32 OIHW -> sign(w) ; out f32.
//
// out[p, co] = sum_{tap,ci} sign(W) * x[ci, p + shift(tap)] over padded
// flattened pixel space (66x66). Single-pass fp16 (rel_err ~2e-4 < 1e-3).
// This round: A halo (full 128 ci) loaded ONCE per CTA; B-fragment LDSMs
// hoisted a full k-slice ahead of their consuming MMAs.
// ============================================================================

#define NPOS_STRIDE 4736ull   // 128 guard + pixels + tail guard
#define POS_BASE    128
#define N_TILES     35        // ceil(66*66 / 128) = 35 tiles of 128 positions
#define HALO        72        // rows of lead guard inside the A smem halo
#define A_ROWS      272       // covers shifts [-67,+67] around 128-row tile

// -------- scratch (zero-initialized device globals; guards stay 0) ----------
__device__ __half g_xh[32ull * NPOS_STRIDE * 128];
__device__ __half g_wb[2 * 9 * 256 * 64];   // [chunk][tap][co][ci64]

// ---------------------------- helpers ---------------------------------------
__device__ __forceinline__ uint32_t smem_u32(const void* p) {
    uint32_t a;
    asm("{ .reg .u64 t; cvta.to.shared.u64 t, %1; cvt.u32.u64 %0, t; }"
        : "=r"(a) : "l"(p));
    return a;
}

#define CP_ASYNC16(dst_u32, src_ptr) \
    asm volatile("cp.async.cg.shared.global [%0], [%1], 16;" \
                 :: "r"(dst_u32), "l"(src_ptr))
#define CP_COMMIT() asm volatile("cp.async.commit_group;" ::: "memory")
#define CP_WAIT0()  asm volatile("cp.async.wait_group 0;" ::: "memory")

__device__ __forceinline__ void ldsm_x4(uint32_t& r0, uint32_t& r1,
                                        uint32_t& r2, uint32_t& r3,
                                        uint32_t addr) {
    asm volatile("ldmatrix.sync.aligned.m8n8.x4.shared.b16 {%0,%1,%2,%3}, [%4];"
                 : "=r"(r0), "=r"(r1), "=r"(r2), "=r"(r3) : "r"(addr));
}

__device__ __forceinline__ void mma_f16(float* c, const uint32_t* a,
                                        uint32_t b0, uint32_t b1) {
    asm volatile(
        "mma.sync.aligned.m16n8k16.row.col.f32.f16.f16.f32 "
        "{%0,%1,%2,%3}, {%4,%5,%6,%7}, {%8,%9}, {%0,%1,%2,%3};"
        : "+f"(c[0]), "+f"(c[1]), "+f"(c[2]), "+f"(c[3])
        : "r"(a[0]), "r"(a[1]), "r"(a[2]), "r"(a[3]), "r"(b0), "r"(b1));
}

// ---------------------------- pre-kernel: weights ----------------------------
__global__ void __launch_bounds__(256) prep_w(const float* __restrict__ w) {
    int idx = blockIdx.x * 256 + threadIdx.x;   // [co][ci][tap] flat
    if (idx >= 256 * 128 * 9) return;
    int co  = idx / 1152;
    int rem = idx - co * 1152;
    int ci  = rem / 9;
    int tap = rem - ci * 9;
    float v = w[idx];
    float s = (v > 0.f) ? 1.f : ((v < 0.f) ? -1.f : 0.f);
    g_wb[(((ci >> 6) * 9 + tap) << 14) + (co << 6) + (ci & 63)] = __float2half_rn(s);
}

// ------------------- pre-kernel: pad + transpose x (fp16) --------------------
__global__ void __launch_bounds__(256) prep_x(const float* __restrict__ x) {
    __shared__ float st[64 * 129];
    const int h = blockIdx.x, n = blockIdx.y, t = threadIdx.x;

    for (int idx = t; idx < 8192; idx += 256) {
        int ci = idx >> 6, w = idx & 63;
        st[w * 129 + ci] = x[(((size_t)n * 128 + ci) * 64 + h) * 64 + w];
    }
    __syncthreads();
    for (int idx = t; idx < 8192; idx += 256) {
        int w = idx >> 7, ci = idx & 127;
        size_t pos = (size_t)n * NPOS_STRIDE + POS_BASE + (size_t)(h + 1) * 66 + (w + 1);
        g_xh[pos * 128 + ci] = __float2half_rn(st[w * 129 + ci]);
    }
}

// ------------------------------- main kernel ---------------------------------
// dynamic smem layout (bytes):
//   A  : [0,     69632)   272 rows x 256B (128 ci), swizzled; loaded ONCE
//   B0 : [69632, 86016)   128 rows x 128B (64 ci), swizzled (double-buffered)
//   B1 : [86016, 102400)
//   D (epilogue, reuses all): 128co x 132 floats = 67584B
#define SM_A     0
#define SM_B0    69632
#define SM_B1    86016
#define SM_TOTAL 102400

__global__ void __launch_bounds__(256, 2)
bconv_hmma(float* __restrict__ out) {
    extern __shared__ char sm[];
    const uint32_t smb = smem_u32(sm);

    const int t    = threadIdx.x;
    const int wid  = t >> 5;
    const int lane = t & 31;
    const int n    = blockIdx.z;
    const int coB  = blockIdx.y;           // 0/1 -> co block of 128
    const int p0   = blockIdx.x * 128;

    const int mw = wid & 1;                // 2 m-halves of 64 pix
    const int nw = wid >> 1;               // 4 n-quarters of 32 co

    // lane-invariant ldmatrix offsets
    const int q  = lane >> 3;
    const int rA = (lane & 7) + ((q & 1) << 3);     // A row-in-tile
    const int cA = q >> 1;                          // A k-half (16B unit)
    const int rB = (lane & 7) + ((lane >> 4) << 3); // B row-in-pair
    const int cB = q & 1;                           // B k-half

    float acc[4][4][4];
#pragma unroll
    for (int i = 0; i < 4; i++)
#pragma unroll
        for (int j = 0; j < 4; j++)
#pragma unroll
            for (int k = 0; k < 4; k++) acc[i][j][k] = 0.f;

    // element offset of halo row 0 (ci0 of current image)
    const size_t xrow0 = ((size_t)n * NPOS_STRIDE + POS_BASE + p0 - HALO) * 128;
    const __half* wbase = g_wb + (coB << 13);   // co block offset

    // ---- prologue: prefetch B(iter 0), then the full A halo (once) ----
    for (int i = t; i < 1024; i += 256) {
        const int r = i >> 3, j = i & 7;
        const uint32_t doff = (uint32_t)(r * 128 + ((j ^ (r & 7)) << 4));
        CP_ASYNC16(smb + SM_B0 + doff, wbase + (i << 3));
    }
    CP_COMMIT();
    // A: 272 rows x 256B, 16 chunks of 16B per row, XOR-swizzled in 16B units
    for (int i = t; i < A_ROWS * 16; i += 256) {
        const int r = i >> 4, j = i & 15;
        const size_t gsrc = xrow0 + (size_t)r * 128 + (j << 3);
        const uint32_t doff = (uint32_t)(r * 256 + ((j ^ (r & 7)) << 4));
        CP_ASYNC16(smb + SM_A + doff, g_xh + gsrc);
    }
    CP_COMMIT();

#pragma unroll 1
    for (int iter = 0; iter < 18; ++iter) {
        const int tap   = iter >> 1;
        const int chunk = iter & 1;

        CP_WAIT0();            // B(iter) landed (iter 0: + A halo)
        __syncthreads();       // frees the other B buffer for prefetch

        if (iter < 17) {       // ---- prefetch next iter's B ----
            const int ni = iter + 1;
            const __half* src = wbase + ((((ni & 1) * 9 + (ni >> 1)) << 14));
            const uint32_t bdst = smb + ((ni & 1) ? SM_B1 : SM_B0);
            for (int i = t; i < 1024; i += 256) {
                const int r = i >> 3, j = i & 7;
                const uint32_t doff = (uint32_t)(r * 128 + ((j ^ (r & 7)) << 4));
                CP_ASYNC16(bdst + doff, src + (i << 3));
            }
            CP_COMMIT();
        }

        // ---- compute tap/chunk ----
        const int s = (tap / 3 - 1) * 66 + (tap % 3 - 1);
        const int aRowBase = mw * 64 + s + HALO;
        const int bRowBase = nw * 32;
        const uint32_t bbase = smb + ((iter & 1) ? SM_B1 : SM_B0);
        const int cbase = chunk << 3;   // A column base in 16B units

        // hoist ALL B fragments for this iter (4 k-slices)
        uint32_t bf[4][4][2];
#pragma unroll
        for (int ks = 0; ks < 4; ks++) {
#pragma unroll
            for (int pr = 0; pr < 2; pr++) {
                const int row = bRowBase + pr * 16 + rB;
                const uint32_t addr = bbase + row * 128 +
                                      (((2 * ks + cB) ^ (row & 7)) << 4);
                ldsm_x4(bf[ks][pr * 2][0], bf[ks][pr * 2][1],
                        bf[ks][pr * 2 + 1][0], bf[ks][pr * 2 + 1][1], addr);
            }
        }

#pragma unroll
        for (int ks = 0; ks < 4; ks++) {
            uint32_t af[4][4];
#pragma unroll
            for (int mt = 0; mt < 4; mt++) {
                const int row = aRowBase + mt * 16 + rA;
                const uint32_t addr = smb + SM_A + row * 256 +
                                      (((cbase + 2 * ks + cA) ^ (row & 7)) << 4);
                ldsm_x4(af[mt][0], af[mt][1], af[mt][2], af[mt][3], addr);
            }
#pragma unroll
            for (int mt = 0; mt < 4; mt++)
#pragma unroll
                for (int nt = 0; nt < 4; nt++)
                    mma_f16(acc[mt][nt], af[mt], bf[ks][nt][0], bf[ks][nt][1]);
        }
    }

    // ---- epilogue: acc -> smem D [co][132] -> coalesced masked gmem stores ----
    __syncthreads();
    float* D = (float*)sm;
    const int gRow = lane >> 2;
    const int gCol = (lane & 3) * 2;
#pragma unroll
    for (int mt = 0; mt < 4; mt++) {
#pragma unroll
        for (int nt = 0; nt < 4; nt++) {
            const int pl  = mw * 64 + mt * 16 + gRow;
            const int col = nw * 32 + nt * 8 + gCol;
            D[col * 132 + pl]           = acc[mt][nt][0];
            D[(col + 1) * 132 + pl]     = acc[mt][nt][1];
            D[col * 132 + pl + 8]       = acc[mt][nt][2];
            D[(col + 1) * 132 + pl + 8] = acc[mt][nt][3];
        }
    }
    __syncthreads();

    for (int i = t; i < 128 * 128; i += 256) {
        const int co_l = i >> 7, p_l = i & 127;
        const int p  = p0 + p_l;
        const int hp = p / 66;
        const int wp = p - hp * 66;
        if (hp >= 1 && hp <= 64 && wp >= 1 && wp <= 64)
            out[(((size_t)n * 256 + coB * 128 + co_l) << 12) +
                ((hp - 1) << 6) + (wp - 1)] = D[co_l * 132 + p_l];
    }
}

// ------------------------------- launcher ------------------------------------
extern "C" void kernel_launch(void* const* d_in, const int* in_sizes, int n_in,
                              void* d_out, int out_size) {
    const float* x = (const float*)d_in[0];
    const float* w = (const float*)d_in[1];
    float* out = (float*)d_out;

    cudaFuncSetAttribute(bconv_hmma, cudaFuncAttributeMaxDynamicSharedMemorySize,
                         SM_TOTAL);

    prep_w<<<1152, 256>>>(w);
    prep_x<<<dim3(64, 32), 256>>>(x);
    bconv_hmma<<<dim3(N_TILES, 2, 32), 256, SM_TOTAL>>>(out);
}

// round 10
// speedup vs baseline: 1.1317x; 1.1317x over previous
#include <cuda_runtime.h>
#include <cuda_fp16.h>
#include <cstdint>

// ============================================================================
// Binarized-weight 3x3 conv, stride 1, pad 1, via implicit GEMM on HMMA
// (mma.sync m16n8k16 fp16 -> fp32 accum; arch-neutral PTX at compute_103).
// x: (32,128,64,64) f32 NCHW ; w: (256,128,3,3) f32 OIHW -> sign(w) ; out f32.
//
// out[p, co] = sum_{tap,ci} sign(W) * x[ci, p + shift(tap)] over padded
// space (66x66). Tile = 2 OUTPUT rows x 64 cols (128 valid positions, zero
// waste): m 0..63 -> row h, m 64..127 -> row h+1 (skip = +2 in padded space,
// folded into aRowBase = mw*66 + s + 67). Single-pass fp16 (~2e-4 rel_err).
// A halo (264 rows x 128 ci) loaded once; B double-buffered via cp.async.
// ============================================================================

#define NPOS_STRIDE 4736ull   // 128 guard + 66*66 + tail guard
#define POS_BASE    128
#define N_TILES     32        // 32 output-row-pairs, zero wasted positions
#define A_ROWS      264       // rows [base-67, base+196] around the tile

// -------- scratch (zero-initialized device globals; guards stay 0) ----------
__device__ __half g_xh[32ull * NPOS_STRIDE * 128];
__device__ __half g_wb[2 * 9 * 256 * 64];   // [chunk][tap][co][ci64]

// ---------------------------- helpers ---------------------------------------
__device__ __forceinline__ uint32_t smem_u32(const void* p) {
    uint32_t a;
    asm("{ .reg .u64 t; cvta.to.shared.u64 t, %1; cvt.u32.u64 %0, t; }"
        : "=r"(a) : "l"(p));
    return a;
}

#define CP_ASYNC16(dst_u32, src_ptr) \
    asm volatile("cp.async.cg.shared.global [%0], [%1], 16;" \
                 :: "r"(dst_u32), "l"(src_ptr))
#define CP_COMMIT() asm volatile("cp.async.commit_group;" ::: "memory")
#define CP_WAIT0()  asm volatile("cp.async.wait_group 0;" ::: "memory")

__device__ __forceinline__ void ldsm_x4(uint32_t& r0, uint32_t& r1,
                                        uint32_t& r2, uint32_t& r3,
                                        uint32_t addr) {
    asm volatile("ldmatrix.sync.aligned.m8n8.x4.shared.b16 {%0,%1,%2,%3}, [%4];"
                 : "=r"(r0), "=r"(r1), "=r"(r2), "=r"(r3) : "r"(addr));
}

__device__ __forceinline__ void mma_f16(float* c, const uint32_t* a,
                                        uint32_t b0, uint32_t b1) {
    asm volatile(
        "mma.sync.aligned.m16n8k16.row.col.f32.f16.f16.f32 "
        "{%0,%1,%2,%3}, {%4,%5,%6,%7}, {%8,%9}, {%0,%1,%2,%3};"
        : "+f"(c[0]), "+f"(c[1]), "+f"(c[2]), "+f"(c[3])
        : "r"(a[0]), "r"(a[1]), "r"(a[2]), "r"(a[3]), "r"(b0), "r"(b1));
}

// ----------------- merged pre-kernel: weights + pad/transpose x --------------
// blocks [0, 2048): prep_x role (h = b & 63, n = b >> 6)
// blocks [2048, 3200): prep_w role
__global__ void __launch_bounds__(256) prep_all(const float* __restrict__ x,
                                                const float* __restrict__ w) {
    const int b = blockIdx.x;
    const int t = threadIdx.x;
    if (b < 2048) {
        __shared__ float st[64 * 129];
        const int h = b & 63, n = b >> 6;
        for (int idx = t; idx < 8192; idx += 256) {
            int ci = idx >> 6, ww = idx & 63;
            st[ww * 129 + ci] = x[(((size_t)n * 128 + ci) * 64 + h) * 64 + ww];
        }
        __syncthreads();
        for (int idx = t; idx < 8192; idx += 256) {
            int ww = idx >> 7, ci = idx & 127;
            size_t pos = (size_t)n * NPOS_STRIDE + POS_BASE +
                         (size_t)(h + 1) * 66 + (ww + 1);
            g_xh[pos * 128 + ci] = __float2half_rn(st[ww * 129 + ci]);
        }
    } else {
        int idx = (b - 2048) * 256 + t;   // [co][ci][tap] flat
        if (idx >= 256 * 128 * 9) return;
        int co  = idx / 1152;
        int rem = idx - co * 1152;
        int ci  = rem / 9;
        int tap = rem - ci * 9;
        float v = w[idx];
        float s = (v > 0.f) ? 1.f : ((v < 0.f) ? -1.f : 0.f);
        g_wb[(((ci >> 6) * 9 + tap) << 14) + (co << 6) + (ci & 63)] =
            __float2half_rn(s);
    }
}

// ------------------------------- main kernel ---------------------------------
// dynamic smem layout (bytes):
//   A  : [0,     67584)   264 rows x 256B (128 ci), swizzled; loaded ONCE
//   B0 : [67584, 83968)   128 rows x 128B (64 ci), swizzled (double-buffered)
//   B1 : [83968, 100352)
//   D (epilogue, reuses A): 128co x 132 floats = 67584B
#define SM_A     0
#define SM_B0    67584
#define SM_B1    83968
#define SM_TOTAL 100352

__global__ void __launch_bounds__(256, 2)
bconv_hmma(float* __restrict__ out) {
    extern __shared__ char sm[];
    const uint32_t smb = smem_u32(sm);

    const int t    = threadIdx.x;
    const int wid  = t >> 5;
    const int lane = t & 31;
    const int n    = blockIdx.z;
    const int coB  = blockIdx.y;           // 0/1 -> co block of 128
    const int tile = blockIdx.x;           // output rows (2*tile, 2*tile+1)

    const int mw = wid & 1;                // 2 m-halves of 64 positions
    const int nw = wid >> 1;               // 4 n-quarters of 32 co

    // lane-invariant ldmatrix offsets
    const int q  = lane >> 3;
    const int rA = (lane & 7) + ((q & 1) << 3);     // A row-in-tile
    const int cA = q >> 1;                          // A k-half (16B unit)
    const int rB = (lane & 7) + ((lane >> 4) << 3); // B row-in-pair
    const int cB = q & 1;                           // B k-half

    float acc[4][4][4];
#pragma unroll
    for (int i = 0; i < 4; i++)
#pragma unroll
        for (int j = 0; j < 4; j++)
#pragma unroll
            for (int k = 0; k < 4; k++) acc[i][j][k] = 0.f;

    // halo row 0 = padded position base-67 = 132*tile  (base = 132*tile + 67)
    const size_t xrow0 = ((size_t)n * NPOS_STRIDE + POS_BASE + 132 * tile) * 128;
    const __half* wbase = g_wb + (coB << 13);   // co block offset

    // ---- prologue: prefetch B(iter 0), then full A halo (once) ----
    for (int i = t; i < 1024; i += 256) {
        const int r = i >> 3, j = i & 7;
        const uint32_t doff = (uint32_t)(r * 128 + ((j ^ (r & 7)) << 4));
        CP_ASYNC16(smb + SM_B0 + doff, wbase + (i << 3));
    }
    CP_COMMIT();
    // A: 264 rows x 256B, 16 units of 16B per row, XOR-swizzled in 16B units
    for (int i = t; i < A_ROWS * 16; i += 256) {
        const int r = i >> 4, j = i & 15;
        const size_t gsrc = xrow0 + (size_t)r * 128 + (j << 3);
        const uint32_t doff = (uint32_t)(r * 256 + ((j ^ (r & 7)) << 4));
        CP_ASYNC16(smb + SM_A + doff, g_xh + gsrc);
    }
    CP_COMMIT();

#pragma unroll 1
    for (int iter = 0; iter < 18; ++iter) {
        const int chunk = iter / 9;
        const int tap   = iter - chunk * 9;

        CP_WAIT0();            // B(iter) landed (iter 0: + A halo)
        __syncthreads();       // frees the other B buffer for prefetch

        if (iter < 17) {       // ---- prefetch next iter's B ----
            const __half* src = wbase + ((iter + 1) << 14);
            const uint32_t bdst = smb + (((iter + 1) & 1) ? SM_B1 : SM_B0);
            for (int i = t; i < 1024; i += 256) {
                const int r = i >> 3, j = i & 7;
                const uint32_t doff = (uint32_t)(r * 128 + ((j ^ (r & 7)) << 4));
                CP_ASYNC16(bdst + doff, src + (i << 3));
            }
            CP_COMMIT();
        }

        // ---- compute tap/chunk ----
        const int s = (tap / 3 - 1) * 66 + (tap % 3 - 1);
        const int aRowBase = mw * 66 + s + 67;   // mw*64 + mw*2 (segment skip)
        const int bRowBase = nw * 32;
        const uint32_t bbase = smb + ((iter & 1) ? SM_B1 : SM_B0);
        const int cbase = chunk << 3;   // A column base in 16B units

#pragma unroll
        for (int ks = 0; ks < 4; ks++) {
            uint32_t bf[4][2];
#pragma unroll
            for (int pr = 0; pr < 2; pr++) {
                const int row = bRowBase + pr * 16 + rB;
                const uint32_t addr = bbase + row * 128 +
                                      (((2 * ks + cB) ^ (row & 7)) << 4);
                ldsm_x4(bf[pr * 2][0], bf[pr * 2][1],
                        bf[pr * 2 + 1][0], bf[pr * 2 + 1][1], addr);
            }
            uint32_t af[4][4];
#pragma unroll
            for (int mt = 0; mt < 4; mt++) {
                const int row = aRowBase + mt * 16 + rA;
                const uint32_t addr = smb + SM_A + row * 256 +
                                      (((cbase + 2 * ks + cA) ^ (row & 7)) << 4);
                ldsm_x4(af[mt][0], af[mt][1], af[mt][2], af[mt][3], addr);
            }
#pragma unroll
            for (int mt = 0; mt < 4; mt++)
#pragma unroll
                for (int nt = 0; nt < 4; nt++)
                    mma_f16(acc[mt][nt], af[mt], bf[nt][0], bf[nt][1]);
        }
    }

    // ---- epilogue: acc -> smem D [co][132] -> coalesced gmem (no masking) ----
    __syncthreads();
    float* D = (float*)sm;
    const int gRow = lane >> 2;
    const int gCol = (lane & 3) * 2;
#pragma unroll
    for (int mt = 0; mt < 4; mt++) {
#pragma unroll
        for (int nt = 0; nt < 4; nt++) {
            const int pl  = mw * 64 + mt * 16 + gRow;
            const int col = nw * 32 + nt * 8 + gCol;
            D[col * 132 + pl]           = acc[mt][nt][0];
            D[(col + 1) * 132 + pl]     = acc[mt][nt][1];
            D[col * 132 + pl + 8]       = acc[mt][nt][2];
            D[(col + 1) * 132 + pl + 8] = acc[mt][nt][3];
        }
    }
    __syncthreads();

    // position p_l: 0..63 -> output row 2*tile, 64..127 -> 2*tile+1; col = p_l&63
    for (int i = t; i < 128 * 128; i += 256) {
        const int co_l = i >> 7, p_l = i & 127;
        const int h = 2 * tile + (p_l >> 6);
        out[(((size_t)n * 256 + coB * 128 + co_l) << 12) + (h << 6) + (p_l & 63)]
            = D[co_l * 132 + p_l];
    }
}

// ------------------------------- launcher ------------------------------------
extern "C" void kernel_launch(void* const* d_in, const int* in_sizes, int n_in,
                              void* d_out, int out_size) {
    const float* x = (const float*)d_in[0];
    const float* w = (const float*)d_in[1];
    float* out = (float*)d_out;

    cudaFuncSetAttribute(bconv_hmma, cudaFuncAttributeMaxDynamicSharedMemorySize,
                         SM_TOTAL);

    prep_all<<<3200, 256>>>(x, w);
    bconv_hmma<<<dim3(N_TILES, 2, 32), 256, SM_TOTAL>>>(out);
}